// round 15
// baseline (speedup 1.0000x reference)
#include <cuda_runtime.h>
#include <math.h>

#define Nn 100000
#define Ee 400000
#define Gg 5000
#define Hh 128
#define ND 52
#define ED 16
#define BK2 16

// ---------------- scratch (static device globals; no runtime allocation) ----------------
__device__ float g_h0[Nn * ND];        // encoded node features (52)
__device__ float g_hA[Nn * Hh];
__device__ float g_hB[Nn * Hh];
__device__ float g_xl[Nn * Hh];
__device__ float g_xr[Nn * Hh];
__device__ float g_e[Ee * ED];         // edge features (input order, staging)
__device__ float g_ec[(Ee + Nn) * ED]; // edge features in CSR order (self-loops embedded)
__device__ float g_w[Ee + Nn];         // per-slot exp(score), layer-specific
__device__ int   g_deg[Nn];
__device__ int   g_off[Nn + 1];
__device__ int   g_cur[Nn];
__device__ int   g_srcs[Ee + Nn];
__device__ int   g_dsts[Ee + Nn];
__device__ int   g_bsums[128];

#define BUF_H0 0
#define BUF_HA 1
#define BUF_HB 2
__device__ __forceinline__ float* bufsel(int id) {
    switch (id) {
        case BUF_H0: return g_h0;
        case BUF_HA: return g_hA;
        default:     return g_hB;
    }
}

// ---------------- zero-init + node encoder (merged) ----------------
__global__ void k_init_nodes(const float* __restrict__ x,
                             const float* __restrict__ atom_emb,
                             const float* __restrict__ bool_emb,
                             const float* __restrict__ Wn,
                             const float* __restrict__ bn,
                             float* __restrict__ dout) {
    int i = blockIdx.x * blockDim.x + threadIdx.x;
    if (i < Gg * Hh) dout[i] = 0.0f;                     // pool output (values >= 0)
    if (i < Nn) g_deg[i] = 0;

    int n = i;
    if (n >= Nn) return;
    const float* xr = x + (size_t)n * 14;
    float* out = g_h0 + (size_t)n * ND;
    int ai = (int)xr[0];
#pragma unroll
    for (int k = 0; k < 16; k++) out[k] = atom_emb[ai * 16 + k];
    float xc[10];
#pragma unroll
    for (int i2 = 0; i2 < 10; i2++) xc[i2] = xr[1 + i2];
#pragma unroll
    for (int j = 0; j < 30; j++) {
        float s = bn[j];
#pragma unroll
        for (int i2 = 0; i2 < 10; i2++) s += xc[i2] * Wn[i2 * 30 + j];
        out[16 + j] = s;
    }
    int b0 = (int)xr[11], b1 = (int)xr[12], b2 = (int)xr[13];
    out[46] = bool_emb[b0 * 2];     out[47] = bool_emb[b0 * 2 + 1];
    out[48] = bool_emb[b1 * 2];     out[49] = bool_emb[b1 * 2 + 1];
    out[50] = bool_emb[b2 * 2];     out[51] = bool_emb[b2 * 2 + 1];
}

// ---------------- edge encoder + in-degree count ----------------
__global__ void k_enc_edges(const float* __restrict__ ea,
                            const int* __restrict__ ei,
                            const float* __restrict__ bond_emb,
                            const float* __restrict__ bool_emb,
                            const float* __restrict__ We,
                            const float* __restrict__ be) {
    int e = blockIdx.x * blockDim.x + threadIdx.x;
    if (e >= Ee) return;
    const float* a = ea + (size_t)e * 6;
    float ev[ED];
    int bi = (int)a[0];
#pragma unroll
    for (int k = 0; k < 8; k++) ev[k] = bond_emb[bi * 8 + k];
    ev[8] = a[1] * We[0] + be[0];
    ev[9] = a[1] * We[1] + be[1];
    int b0 = (int)a[2], b1 = (int)a[3], b2 = (int)a[4];
    ev[10] = bool_emb[b0 * 2]; ev[11] = bool_emb[b0 * 2 + 1];
    ev[12] = bool_emb[b1 * 2]; ev[13] = bool_emb[b1 * 2 + 1];
    ev[14] = bool_emb[b2 * 2]; ev[15] = bool_emb[b2 * 2 + 1];
    float* out = g_e + (size_t)e * ED;
#pragma unroll
    for (int k = 0; k < ED; k++) out[k] = ev[k];
    atomicAdd(&g_deg[ei[Ee + e]], 1);
}

// ---------------- CSR scan over (deg+1) ----------------
__global__ void k_scan1() {
    __shared__ int s[1024];
    int i = blockIdx.x * 1024 + threadIdx.x;
    int d = (i < Nn) ? g_deg[i] : 0;
    int v = (i < Nn) ? d + 1 : 0;            // +1 slot for the self-loop
    s[threadIdx.x] = v;
    __syncthreads();
    for (int o = 1; o < 1024; o <<= 1) {
        int t = (threadIdx.x >= o) ? s[threadIdx.x - o] : 0;
        __syncthreads();
        s[threadIdx.x] += t;
        __syncthreads();
    }
    if (i < Nn) g_off[i] = s[threadIdx.x] - v;  // exclusive within block
    if (threadIdx.x == 1023) g_bsums[blockIdx.x] = s[1023];
}

// merged scan2+scan3 + self-loop src/dst fill
__global__ void k_scan23() {
    __shared__ int pre;
    int b = blockIdx.x;
    if (threadIdx.x == 0) pre = 0;
    __syncthreads();
    int v = (threadIdx.x < b) ? g_bsums[threadIdx.x] : 0;   // b <= 97 < 1024
#pragma unroll
    for (int o = 16; o > 0; o >>= 1) v += __shfl_xor_sync(0xffffffff, v, o);
    if ((threadIdx.x & 31) == 0 && v) atomicAdd(&pre, v);
    __syncthreads();
    int i = b * 1024 + threadIdx.x;
    if (i < Nn) {
        int o = g_off[i] + pre;
        g_off[i] = o;
        g_cur[i] = o;
        int slot = o + g_deg[i];             // last slot of node i = self-loop
        g_srcs[slot] = i;
        g_dsts[slot] = i;
    }
    if (i == 0) g_off[Nn] = Ee + Nn;
}

// scatter + permute edge features into CSR order
__global__ void k_scatter(const int* __restrict__ ei) {
    int e = blockIdx.x * blockDim.x + threadIdx.x;
    if (e >= Ee) return;
    int dst = ei[Ee + e];
    int p = atomicAdd(&g_cur[dst], 1);
    g_srcs[p] = ei[e];
    g_dsts[p] = dst;
    const float4* src4 = (const float4*)(g_e + (size_t)e * ED);
    float4* dst4 = (float4*)(g_ec + (size_t)p * ED);
    dst4[0] = src4[0]; dst4[1] = src4[1]; dst4[2] = src4[2]; dst4[3] = src4[3];
}

// ---------------- self-loop attrs: mean of in-edge rows, contention-free ----------------
__global__ void k_loopattr() {
    int tid = threadIdx.x;
    int warp = tid >> 5, lane = tid & 31;
    int n = blockIdx.x * (blockDim.x >> 5) + warp;
    if (n >= Nn) return;
    int beg = g_off[n];
    int deg = g_off[n + 1] - beg - 1;        // slots minus self
    int f = lane & 15, rh = lane >> 4;
    float s = 0.f;
    for (int r = rh; r < deg; r += 2)
        s += g_ec[(size_t)(beg + r) * ED + f];
    s += __shfl_xor_sync(0xffffffff, s, 16);
    if (lane < 16) {
        float inv = 1.0f / fmaxf((float)deg, 1.0f);
        g_ec[(size_t)(beg + deg) * ED + lane] = s * inv;
    }
}

// ---------------- fused fp32 GEMM pair, 2-stage cp.async (measured best: R13) ----------
__global__ __launch_bounds__(256) void k_gemm2(int a_id, int K,
                        const float* __restrict__ Wl, const float* __restrict__ bl,
                        const float* __restrict__ Wr, const float* __restrict__ br) {
    __shared__ float As[2][BK2][68];     // transposed A tiles (8.7 KB)
    __shared__ float Ws[2][BK2][256];    // W tiles (32.8 KB)
    const float* A = bufsel(a_id);

    int tid = threadIdx.x;
    int tx = tid & 31, ty = tid >> 5;
    int row0 = blockIdx.x * 64;

    float acc[8][8];
#pragma unroll
    for (int i = 0; i < 8; i++)
#pragma unroll
        for (int j = 0; j < 8; j++) acc[i][j] = 0.0f;

    int ar = tid >> 2;                 // 0..63
    int ac4 = (tid & 3) << 2;          // 0,4,8,12
    int gr = row0 + ar;
    const float* arow = A + (size_t)gr * K;

    float4 blv = *(const float4*)&bl[tx * 4];
    float4 brv = *(const float4*)&br[tx * 4];

    auto loadA = [&](int kb) -> float4 {
        float4 v = make_float4(0.f, 0.f, 0.f, 0.f);
        int gk = kb + ac4;
        if (gr < Nn) {
            if (gk + 3 < K) v = *(const float4*)(arow + gk);
            else {
                if (gk     < K) v.x = arow[gk];
                if (gk + 1 < K) v.y = arow[gk + 1];
                if (gk + 2 < K) v.z = arow[gk + 2];
            }
        }
        return v;
    };
    auto stsA = [&](float4 v, int buf) {
        As[buf][ac4 + 0][ar] = v.x;
        As[buf][ac4 + 1][ar] = v.y;
        As[buf][ac4 + 2][ar] = v.z;
        As[buf][ac4 + 3][ar] = v.w;
    };
    auto cpW = [&](int kb, int buf) {
#pragma unroll
        for (int i = 0; i < 4; i++) {
            int f = tid + i * 256;
            int k = f >> 6, c4 = (f & 63) << 2;
            int gk = kb + k;
            bool ok = (gk < K);
            const float* src = !ok ? Wl
                             : (c4 < 128) ? (Wl + (size_t)gk * 128 + c4)
                                          : (Wr + (size_t)gk * 128 + (c4 - 128));
            unsigned dst = (unsigned)__cvta_generic_to_shared(&Ws[buf][k][c4]);
            int sz = ok ? 16 : 0;
            asm volatile("cp.async.cg.shared.global [%0], [%1], 16, %2;\n"
                         :: "r"(dst), "l"(src), "r"(sz));
        }
    };

    float4 ap = loadA(0);
    cpW(0, 0);
    asm volatile("cp.async.commit_group;\n");
    stsA(ap, 0);
    asm volatile("cp.async.wait_group 0;\n");
    __syncthreads();

    int nst = (K + BK2 - 1) / BK2;
    for (int s = 0; s < nst; s++) {
        int cur = s & 1, nxt = cur ^ 1;
        bool more = (s + 1 < nst);
        if (more) {
            ap = loadA((s + 1) * BK2);
            cpW((s + 1) * BK2, nxt);
            asm volatile("cp.async.commit_group;\n");
        }
#pragma unroll 2
        for (int k = 0; k < BK2; k++) {
            float4 a0 = *(const float4*)&As[cur][k][ty * 8];
            float4 a1 = *(const float4*)&As[cur][k][ty * 8 + 4];
            float4 w0 = *(const float4*)&Ws[cur][k][tx * 4];
            float4 w1 = *(const float4*)&Ws[cur][k][128 + tx * 4];
            float av[8] = {a0.x, a0.y, a0.z, a0.w, a1.x, a1.y, a1.z, a1.w};
            float wv[8] = {w0.x, w0.y, w0.z, w0.w, w1.x, w1.y, w1.z, w1.w};
#pragma unroll
            for (int i = 0; i < 8; i++)
#pragma unroll
                for (int j = 0; j < 8; j++) acc[i][j] += av[i] * wv[j];
        }
        if (more) {
            stsA(ap, nxt);
            asm volatile("cp.async.wait_group 0;\n");
        }
        __syncthreads();
    }

#pragma unroll
    for (int i = 0; i < 8; i++) {
        int r = row0 + ty * 8 + i;
        if (r < Nn) {
            float4 ol = make_float4(acc[i][0] + blv.x, acc[i][1] + blv.y,
                                    acc[i][2] + blv.z, acc[i][3] + blv.w);
            float4 orr = make_float4(acc[i][4] + brv.x, acc[i][5] + brv.y,
                                     acc[i][6] + brv.z, acc[i][7] + brv.w);
            *(float4*)(g_xl + (size_t)r * Hh + tx * 4) = ol;
            *(float4*)(g_xr + (size_t)r * Hh + tx * 4) = orr;
        }
    }
}

// ---------------- edge-parallel attention scores: 8 slots per warp ----------------------
// All 16 xl/xr row loads issued up-front (MLP ~16/warp vs 4 before) to cover the DRAM
// misses (xl+xr+e working set 134MB > L2). e-rows stream in-loop.
__global__ __launch_bounds__(256) void k_score(const float* __restrict__ Wedge,
                                               const float* __restrict__ att) {
    __shared__ float Ws[ED][Hh];
    __shared__ float atts[Hh];
    int tid = threadIdx.x;
    for (int t = tid; t < ED * Hh; t += blockDim.x) Ws[t >> 7][t & 127] = Wedge[t];
    if (tid < Hh) atts[tid] = att[tid];
    __syncthreads();

    const int total = Ee + Nn;
    int warp = (blockIdx.x * blockDim.x + tid) >> 5;
    int lane = tid & 31;
    int base = warp * 8;
    if (base >= total) return;
    int c0 = lane * 4;
    const float4 at4 = *(const float4*)&atts[c0];
    const float* xl = g_xl;
    const float* xr = g_xr;

    int idx[8];
#pragma unroll
    for (int q = 0; q < 8; q++) idx[q] = min(base + q, total - 1);

    float4 xlv[8], xrv[8];
#pragma unroll
    for (int q = 0; q < 8; q++) {
        int s = g_srcs[idx[q]];
        xlv[q] = *(const float4*)(xl + (size_t)s * Hh + c0);
    }
#pragma unroll
    for (int q = 0; q < 8; q++) {
        int d = g_dsts[idx[q]];
        xrv[q] = *(const float4*)(xr + (size_t)d * Hh + c0);
    }

    float p[8];
#pragma unroll
    for (int q = 0; q < 8; q++) {
        const float4* ep = (const float4*)(g_ec + (size_t)idx[q] * ED);
        float4 e0 = ep[0], e1 = ep[1], e2 = ep[2], e3 = ep[3];
        float ev[ED] = {e0.x, e0.y, e0.z, e0.w, e1.x, e1.y, e1.z, e1.w,
                        e2.x, e2.y, e2.z, e2.w, e3.x, e3.y, e3.z, e3.w};
        float l0 = 0.f, l1 = 0.f, l2 = 0.f, l3 = 0.f;
#pragma unroll
        for (int j = 0; j < ED; j++) {
            const float4 wj = *(const float4*)&Ws[j][c0];
            float e = ev[j];
            l0 += e * wj.x; l1 += e * wj.y; l2 += e * wj.z; l3 += e * wj.w;
        }
        float m0 = xlv[q].x + xrv[q].x + l0, m1 = xlv[q].y + xrv[q].y + l1;
        float m2 = xlv[q].z + xrv[q].z + l2, m3 = xlv[q].w + xrv[q].w + l3;
        m0 = m0 > 0.f ? m0 : 0.2f * m0;  m1 = m1 > 0.f ? m1 : 0.2f * m1;
        m2 = m2 > 0.f ? m2 : 0.2f * m2;  m3 = m3 > 0.f ? m3 : 0.2f * m3;
        p[q] = m0 * at4.x + m1 * at4.y + m2 * at4.z + m3 * at4.w;
    }
#pragma unroll
    for (int o = 16; o > 0; o >>= 1) {
        p[0] += __shfl_xor_sync(0xffffffff, p[0], o);
        p[1] += __shfl_xor_sync(0xffffffff, p[1], o);
        p[2] += __shfl_xor_sync(0xffffffff, p[2], o);
        p[3] += __shfl_xor_sync(0xffffffff, p[3], o);
        p[4] += __shfl_xor_sync(0xffffffff, p[4], o);
        p[5] += __shfl_xor_sync(0xffffffff, p[5], o);
        p[6] += __shfl_xor_sync(0xffffffff, p[6], o);
        p[7] += __shfl_xor_sync(0xffffffff, p[7], o);
    }
    if (lane == 0) {
#pragma unroll
        for (int q = 0; q < 8; q++)
            if (base + q < total) g_w[base + q] = __expf(p[q]);
    }
}

// ---------------- per-node aggregation: warp/node, 4-way slot unroll --------------------
__global__ void k_agg(const float* __restrict__ bias, int hout_id,
                      int dopool, const int* __restrict__ batch, float* __restrict__ dout) {
    int tid = threadIdx.x;
    int warp = tid >> 5, lane = tid & 31;
    int n = blockIdx.x * (blockDim.x >> 5) + warp;
    if (n >= Nn) return;
    int c0 = lane * 4;
    const float* xl = g_xl;
    float* hout = bufsel(hout_id);

    float s[4] = {0.f, 0.f, 0.f, 0.f};
    float a0[4] = {0.f, 0.f, 0.f, 0.f};
    float a1[4] = {0.f, 0.f, 0.f, 0.f};
    float a2[4] = {0.f, 0.f, 0.f, 0.f};
    float a3[4] = {0.f, 0.f, 0.f, 0.f};
    int beg = g_off[n], end = g_off[n + 1];

    for (int it = beg; it < end; it += 4) {
#pragma unroll
        for (int q = 0; q < 4; q++) {
            int iq = it + q;
            bool ok = (iq < end);
            int idx = ok ? iq : (end - 1);
            int src = g_srcs[idx];
            float w = ok ? g_w[idx] : 0.f;
            float4 v = *(const float4*)(xl + (size_t)src * Hh + c0);
            s[q] += w;
            a0[q] += w * v.x; a1[q] += w * v.y; a2[q] += w * v.z; a3[q] += w * v.w;
        }
    }

    float inv = 1.0f / (s[0] + s[1] + s[2] + s[3]);
    float o0 = fmaxf((a0[0] + a0[1] + a0[2] + a0[3]) * inv + bias[c0],     0.0f);
    float o1 = fmaxf((a1[0] + a1[1] + a1[2] + a1[3]) * inv + bias[c0 + 1], 0.0f);
    float o2 = fmaxf((a2[0] + a2[1] + a2[2] + a2[3]) * inv + bias[c0 + 2], 0.0f);
    float o3 = fmaxf((a3[0] + a3[1] + a3[2] + a3[3]) * inv + bias[c0 + 3], 0.0f);
    *(float4*)(hout + (size_t)n * Hh + c0) = make_float4(o0, o1, o2, o3);

    if (dopool) {
        int b = batch[n];
        int* dp = (int*)(dout + (size_t)b * Hh + c0);
        atomicMax(dp,     __float_as_int(o0));
        atomicMax(dp + 1, __float_as_int(o1));
        atomicMax(dp + 2, __float_as_int(o2));
        atomicMax(dp + 3, __float_as_int(o3));
    }
}

// ---------------- host launcher (kernel launches only; graph-capture safe) ----------------
extern "C" void kernel_launch(void* const* d_in, const int* in_sizes, int n_in,
                              void* d_out, int out_size) {
    const float* x        = (const float*)d_in[0];
    const int*   ei       = (const int*)d_in[1];
    const float* ea       = (const float*)d_in[2];
    const int*   batch    = (const int*)d_in[3];
    const float* atom_emb = (const float*)d_in[4];
    const float* bond_emb = (const float*)d_in[5];
    const float* bool_emb = (const float*)d_in[6];
    const float* Wn  = (const float*)d_in[7];
    const float* bn  = (const float*)d_in[8];
    const float* We  = (const float*)d_in[9];
    const float* be  = (const float*)d_in[10];
    const float* Wl1 = (const float*)d_in[11];
    const float* bl1 = (const float*)d_in[12];
    const float* Wr1 = (const float*)d_in[13];
    const float* br1 = (const float*)d_in[14];
    const float* Wedge1 = (const float*)d_in[15];
    const float* att1   = (const float*)d_in[16];
    const float* bias1  = (const float*)d_in[17];
    const float* Wl2 = (const float*)d_in[18];
    const float* bl2 = (const float*)d_in[19];
    const float* Wr2 = (const float*)d_in[20];
    const float* br2 = (const float*)d_in[21];
    const float* Wedge2 = (const float*)d_in[22];
    const float* att2   = (const float*)d_in[23];
    const float* bias2  = (const float*)d_in[24];
    float* out = (float*)d_out;

    int gm = (Nn + 63) / 64;
    int ga = (Nn + 7) / 8;
    int nb = (Nn + 1023) / 1024;
    int gs = ((Ee + Nn + 7) / 8 * 32 + 255) / 256;   // k_score: warp per 8 slots

    // prep; layer-1 GEMM kept as 4th launch (ncu window) for round-over-round comparison
    k_init_nodes<<<(Gg * Hh + 255) / 256, 256>>>(x, atom_emb, bool_emb, Wn, bn, out);
    k_enc_edges<<<(Ee + 255) / 256, 256>>>(ea, ei, bond_emb, bool_emb, We, be);
    k_scan1<<<nb, 1024>>>();
    k_gemm2<<<gm, 256>>>(BUF_H0, ND, Wl1, bl1, Wr1, br1);       // layer 1 GEMM (4th launch)
    k_scan23<<<nb, 1024>>>();
    k_scatter<<<(Ee + 255) / 256, 256>>>(ei);
    k_loopattr<<<ga, 256>>>();

    // layer 1: scores then aggregate
    k_score<<<gs, 256>>>(Wedge1, att1);
    k_agg<<<ga, 256>>>(bias1, BUF_HA, 0, batch, out);

    // layer 2 (shared weights W*2)
    k_gemm2<<<gm, 256>>>(BUF_HA, Hh, Wl2, bl2, Wr2, br2);
    k_score<<<gs, 256>>>(Wedge2, att2);
    k_agg<<<ga, 256>>>(bias2, BUF_HB, 0, batch, out);

    // layer 3 (shared weights W*2) + fused global max pool
    k_gemm2<<<gm, 256>>>(BUF_HB, Hh, Wl2, bl2, Wr2, br2);
    k_score<<<gs, 256>>>(Wedge2, att2);
    k_agg<<<ga, 256>>>(bias2, BUF_HA, 1, batch, out);
}

// round 16
// speedup vs baseline: 2.0235x; 2.0235x over previous
#include <cuda_runtime.h>
#include <math.h>

#define Nn 100000
#define Ee 400000
#define Gg 5000
#define Hh 128
#define ND 52
#define ED 16
#define BK2 16

// ---------------- scratch (static device globals; no runtime allocation) ----------------
__device__ float g_h0[Nn * ND];        // encoded node features (52)
__device__ float g_hA[Nn * Hh];
__device__ float g_hB[Nn * Hh];
__device__ float g_xl[Nn * Hh];
__device__ float g_xr[Nn * Hh];
__device__ float g_e[Ee * ED];         // edge features (input order, staging)
__device__ float g_ec[(Ee + Nn) * ED]; // edge features in CSR order (self-loops embedded)
__device__ float g_w[Ee + Nn];         // per-slot exp(score), layer-specific
__device__ int   g_deg[Nn];
__device__ int   g_off[Nn + 1];
__device__ int   g_cur[Nn];
__device__ int   g_srcs[Ee + Nn];
__device__ int   g_dsts[Ee + Nn];
__device__ int   g_bsums[128];

#define BUF_H0 0
#define BUF_HA 1
#define BUF_HB 2
__device__ __forceinline__ float* bufsel(int id) {
    switch (id) {
        case BUF_H0: return g_h0;
        case BUF_HA: return g_hA;
        default:     return g_hB;
    }
}

// ---------------- zero-init + node encoder (merged) ----------------
__global__ void k_init_nodes(const float* __restrict__ x,
                             const float* __restrict__ atom_emb,
                             const float* __restrict__ bool_emb,
                             const float* __restrict__ Wn,
                             const float* __restrict__ bn,
                             float* __restrict__ dout) {
    int i = blockIdx.x * blockDim.x + threadIdx.x;
    if (i < Gg * Hh) dout[i] = 0.0f;                     // pool output (values >= 0)
    if (i < Nn) g_deg[i] = 0;

    int n = i;
    if (n >= Nn) return;
    const float* xr = x + (size_t)n * 14;
    float* out = g_h0 + (size_t)n * ND;
    int ai = (int)xr[0];
#pragma unroll
    for (int k = 0; k < 16; k++) out[k] = atom_emb[ai * 16 + k];
    float xc[10];
#pragma unroll
    for (int i2 = 0; i2 < 10; i2++) xc[i2] = xr[1 + i2];
#pragma unroll
    for (int j = 0; j < 30; j++) {
        float s = bn[j];
#pragma unroll
        for (int i2 = 0; i2 < 10; i2++) s += xc[i2] * Wn[i2 * 30 + j];
        out[16 + j] = s;
    }
    int b0 = (int)xr[11], b1 = (int)xr[12], b2 = (int)xr[13];
    out[46] = bool_emb[b0 * 2];     out[47] = bool_emb[b0 * 2 + 1];
    out[48] = bool_emb[b1 * 2];     out[49] = bool_emb[b1 * 2 + 1];
    out[50] = bool_emb[b2 * 2];     out[51] = bool_emb[b2 * 2 + 1];
}

// ---------------- edge encoder + in-degree count ----------------
__global__ void k_enc_edges(const float* __restrict__ ea,
                            const int* __restrict__ ei,
                            const float* __restrict__ bond_emb,
                            const float* __restrict__ bool_emb,
                            const float* __restrict__ We,
                            const float* __restrict__ be) {
    int e = blockIdx.x * blockDim.x + threadIdx.x;
    if (e >= Ee) return;
    const float* a = ea + (size_t)e * 6;
    float ev[ED];
    int bi = (int)a[0];
#pragma unroll
    for (int k = 0; k < 8; k++) ev[k] = bond_emb[bi * 8 + k];
    ev[8] = a[1] * We[0] + be[0];
    ev[9] = a[1] * We[1] + be[1];
    int b0 = (int)a[2], b1 = (int)a[3], b2 = (int)a[4];
    ev[10] = bool_emb[b0 * 2]; ev[11] = bool_emb[b0 * 2 + 1];
    ev[12] = bool_emb[b1 * 2]; ev[13] = bool_emb[b1 * 2 + 1];
    ev[14] = bool_emb[b2 * 2]; ev[15] = bool_emb[b2 * 2 + 1];
    float* out = g_e + (size_t)e * ED;
#pragma unroll
    for (int k = 0; k < ED; k++) out[k] = ev[k];
    atomicAdd(&g_deg[ei[Ee + e]], 1);
}

// ---------------- CSR scan over (deg+1) ----------------
__global__ void k_scan1() {
    __shared__ int s[1024];
    int i = blockIdx.x * 1024 + threadIdx.x;
    int d = (i < Nn) ? g_deg[i] : 0;
    int v = (i < Nn) ? d + 1 : 0;            // +1 slot for the self-loop
    s[threadIdx.x] = v;
    __syncthreads();
    for (int o = 1; o < 1024; o <<= 1) {
        int t = (threadIdx.x >= o) ? s[threadIdx.x - o] : 0;
        __syncthreads();
        s[threadIdx.x] += t;
        __syncthreads();
    }
    if (i < Nn) g_off[i] = s[threadIdx.x] - v;  // exclusive within block
    if (threadIdx.x == 1023) g_bsums[blockIdx.x] = s[1023];
}

// merged scan2+scan3 + self-loop src/dst fill
__global__ void k_scan23() {
    __shared__ int pre;
    int b = blockIdx.x;
    if (threadIdx.x == 0) pre = 0;
    __syncthreads();
    int v = (threadIdx.x < b) ? g_bsums[threadIdx.x] : 0;   // b <= 97 < 1024
#pragma unroll
    for (int o = 16; o > 0; o >>= 1) v += __shfl_xor_sync(0xffffffff, v, o);
    if ((threadIdx.x & 31) == 0 && v) atomicAdd(&pre, v);
    __syncthreads();
    int i = b * 1024 + threadIdx.x;
    if (i < Nn) {
        int o = g_off[i] + pre;
        g_off[i] = o;
        g_cur[i] = o;
        int slot = o + g_deg[i];             // last slot of node i = self-loop
        g_srcs[slot] = i;
        g_dsts[slot] = i;
    }
    if (i == 0) g_off[Nn] = Ee + Nn;
}

// scatter + permute edge features into CSR order
__global__ void k_scatter(const int* __restrict__ ei) {
    int e = blockIdx.x * blockDim.x + threadIdx.x;
    if (e >= Ee) return;
    int dst = ei[Ee + e];
    int p = atomicAdd(&g_cur[dst], 1);
    g_srcs[p] = ei[e];
    g_dsts[p] = dst;
    const float4* src4 = (const float4*)(g_e + (size_t)e * ED);
    float4* dst4 = (float4*)(g_ec + (size_t)p * ED);
    dst4[0] = src4[0]; dst4[1] = src4[1]; dst4[2] = src4[2]; dst4[3] = src4[3];
}

// ---------------- self-loop attrs: mean of in-edge rows, contention-free ----------------
__global__ void k_loopattr() {
    int tid = threadIdx.x;
    int warp = tid >> 5, lane = tid & 31;
    int n = blockIdx.x * (blockDim.x >> 5) + warp;
    if (n >= Nn) return;
    int beg = g_off[n];
    int deg = g_off[n + 1] - beg - 1;        // slots minus self
    int f = lane & 15, rh = lane >> 4;
    float s = 0.f;
    for (int r = rh; r < deg; r += 2)
        s += g_ec[(size_t)(beg + r) * ED + f];
    s += __shfl_xor_sync(0xffffffff, s, 16);
    if (lane < 16) {
        float inv = 1.0f / fmaxf((float)deg, 1.0f);
        g_ec[(size_t)(beg + deg) * ED + lane] = s * inv;
    }
}

// ---------------- fused fp32 GEMM pair, 2-stage cp.async (measured best: R13) ----------
__global__ __launch_bounds__(256) void k_gemm2(int a_id, int K,
                        const float* __restrict__ Wl, const float* __restrict__ bl,
                        const float* __restrict__ Wr, const float* __restrict__ br) {
    __shared__ float As[2][BK2][68];     // transposed A tiles (8.7 KB)
    __shared__ float Ws[2][BK2][256];    // W tiles (32.8 KB)
    const float* A = bufsel(a_id);

    int tid = threadIdx.x;
    int tx = tid & 31, ty = tid >> 5;
    int row0 = blockIdx.x * 64;

    float acc[8][8];
#pragma unroll
    for (int i = 0; i < 8; i++)
#pragma unroll
        for (int j = 0; j < 8; j++) acc[i][j] = 0.0f;

    int ar = tid >> 2;                 // 0..63
    int ac4 = (tid & 3) << 2;          // 0,4,8,12
    int gr = row0 + ar;
    const float* arow = A + (size_t)gr * K;

    float4 blv = *(const float4*)&bl[tx * 4];
    float4 brv = *(const float4*)&br[tx * 4];

    auto loadA = [&](int kb) -> float4 {
        float4 v = make_float4(0.f, 0.f, 0.f, 0.f);
        int gk = kb + ac4;
        if (gr < Nn) {
            if (gk + 3 < K) v = *(const float4*)(arow + gk);
            else {
                if (gk     < K) v.x = arow[gk];
                if (gk + 1 < K) v.y = arow[gk + 1];
                if (gk + 2 < K) v.z = arow[gk + 2];
            }
        }
        return v;
    };
    auto stsA = [&](float4 v, int buf) {
        As[buf][ac4 + 0][ar] = v.x;
        As[buf][ac4 + 1][ar] = v.y;
        As[buf][ac4 + 2][ar] = v.z;
        As[buf][ac4 + 3][ar] = v.w;
    };
    auto cpW = [&](int kb, int buf) {
#pragma unroll
        for (int i = 0; i < 4; i++) {
            int f = tid + i * 256;
            int k = f >> 6, c4 = (f & 63) << 2;
            int gk = kb + k;
            bool ok = (gk < K);
            const float* src = !ok ? Wl
                             : (c4 < 128) ? (Wl + (size_t)gk * 128 + c4)
                                          : (Wr + (size_t)gk * 128 + (c4 - 128));
            unsigned dst = (unsigned)__cvta_generic_to_shared(&Ws[buf][k][c4]);
            int sz = ok ? 16 : 0;
            asm volatile("cp.async.cg.shared.global [%0], [%1], 16, %2;\n"
                         :: "r"(dst), "l"(src), "r"(sz));
        }
    };

    float4 ap = loadA(0);
    cpW(0, 0);
    asm volatile("cp.async.commit_group;\n");
    stsA(ap, 0);
    asm volatile("cp.async.wait_group 0;\n");
    __syncthreads();

    int nst = (K + BK2 - 1) / BK2;
    for (int s = 0; s < nst; s++) {
        int cur = s & 1, nxt = cur ^ 1;
        bool more = (s + 1 < nst);
        if (more) {
            ap = loadA((s + 1) * BK2);
            cpW((s + 1) * BK2, nxt);
            asm volatile("cp.async.commit_group;\n");
        }
#pragma unroll 2
        for (int k = 0; k < BK2; k++) {
            float4 a0 = *(const float4*)&As[cur][k][ty * 8];
            float4 a1 = *(const float4*)&As[cur][k][ty * 8 + 4];
            float4 w0 = *(const float4*)&Ws[cur][k][tx * 4];
            float4 w1 = *(const float4*)&Ws[cur][k][128 + tx * 4];
            float av[8] = {a0.x, a0.y, a0.z, a0.w, a1.x, a1.y, a1.z, a1.w};
            float wv[8] = {w0.x, w0.y, w0.z, w0.w, w1.x, w1.y, w1.z, w1.w};
#pragma unroll
            for (int i = 0; i < 8; i++)
#pragma unroll
                for (int j = 0; j < 8; j++) acc[i][j] += av[i] * wv[j];
        }
        if (more) {
            stsA(ap, nxt);
            asm volatile("cp.async.wait_group 0;\n");
        }
        __syncthreads();
    }

#pragma unroll
    for (int i = 0; i < 8; i++) {
        int r = row0 + ty * 8 + i;
        if (r < Nn) {
            float4 ol = make_float4(acc[i][0] + blv.x, acc[i][1] + blv.y,
                                    acc[i][2] + blv.z, acc[i][3] + blv.w);
            float4 orr = make_float4(acc[i][4] + brv.x, acc[i][5] + brv.y,
                                     acc[i][6] + brv.z, acc[i][7] + brv.w);
            *(float4*)(g_xl + (size_t)r * Hh + tx * 4) = ol;
            *(float4*)(g_xr + (size_t)r * Hh + tx * 4) = orr;
        }
    }
}

// ---------------- edge-parallel attention scores: 4 slots per warp (measured best) ------
__global__ __launch_bounds__(256) void k_score(const float* __restrict__ Wedge,
                                               const float* __restrict__ att) {
    __shared__ float Ws[ED][Hh];
    __shared__ float atts[Hh];
    int tid = threadIdx.x;
    for (int t = tid; t < ED * Hh; t += blockDim.x) Ws[t >> 7][t & 127] = Wedge[t];
    if (tid < Hh) atts[tid] = att[tid];
    __syncthreads();

    const int total = Ee + Nn;
    int warp = (blockIdx.x * blockDim.x + tid) >> 5;
    int lane = tid & 31;
    int base = warp * 4;
    if (base >= total) return;
    int c0 = lane * 4;
    const float4 at4 = *(const float4*)&atts[c0];
    const float* xl = g_xl;
    const float* xr = g_xr;

    int i0 = base;
    int i1 = min(base + 1, total - 1);
    int i2 = min(base + 2, total - 1);
    int i3 = min(base + 3, total - 1);

    int s0 = g_srcs[i0], s1 = g_srcs[i1], s2 = g_srcs[i2], s3 = g_srcs[i3];
    int d0 = g_dsts[i0], d1 = g_dsts[i1], d2 = g_dsts[i2], d3 = g_dsts[i3];

    float4 xl0 = *(const float4*)(xl + (size_t)s0 * Hh + c0);
    float4 xl1 = *(const float4*)(xl + (size_t)s1 * Hh + c0);
    float4 xl2 = *(const float4*)(xl + (size_t)s2 * Hh + c0);
    float4 xl3 = *(const float4*)(xl + (size_t)s3 * Hh + c0);
    float4 xr0 = *(const float4*)(xr + (size_t)d0 * Hh + c0);
    float4 xr1 = *(const float4*)(xr + (size_t)d1 * Hh + c0);
    float4 xr2 = *(const float4*)(xr + (size_t)d2 * Hh + c0);
    float4 xr3 = *(const float4*)(xr + (size_t)d3 * Hh + c0);

    float p[4];
#pragma unroll
    for (int q = 0; q < 4; q++) {
        int iq = (q == 0) ? i0 : (q == 1) ? i1 : (q == 2) ? i2 : i3;
        const float4* ep = (const float4*)(g_ec + (size_t)iq * ED);
        float4 e0 = ep[0], e1 = ep[1], e2 = ep[2], e3 = ep[3];
        float ev[ED] = {e0.x, e0.y, e0.z, e0.w, e1.x, e1.y, e1.z, e1.w,
                        e2.x, e2.y, e2.z, e2.w, e3.x, e3.y, e3.z, e3.w};
        float l0 = 0.f, l1 = 0.f, l2 = 0.f, l3 = 0.f;
#pragma unroll
        for (int j = 0; j < ED; j++) {
            const float4 wj = *(const float4*)&Ws[j][c0];
            float e = ev[j];
            l0 += e * wj.x; l1 += e * wj.y; l2 += e * wj.z; l3 += e * wj.w;
        }
        float4 a = (q == 0) ? xl0 : (q == 1) ? xl1 : (q == 2) ? xl2 : xl3;
        float4 b = (q == 0) ? xr0 : (q == 1) ? xr1 : (q == 2) ? xr2 : xr3;
        float m0 = a.x + b.x + l0, m1 = a.y + b.y + l1;
        float m2 = a.z + b.z + l2, m3 = a.w + b.w + l3;
        m0 = m0 > 0.f ? m0 : 0.2f * m0;  m1 = m1 > 0.f ? m1 : 0.2f * m1;
        m2 = m2 > 0.f ? m2 : 0.2f * m2;  m3 = m3 > 0.f ? m3 : 0.2f * m3;
        p[q] = m0 * at4.x + m1 * at4.y + m2 * at4.z + m3 * at4.w;
    }
#pragma unroll
    for (int o = 16; o > 0; o >>= 1) {
        p[0] += __shfl_xor_sync(0xffffffff, p[0], o);
        p[1] += __shfl_xor_sync(0xffffffff, p[1], o);
        p[2] += __shfl_xor_sync(0xffffffff, p[2], o);
        p[3] += __shfl_xor_sync(0xffffffff, p[3], o);
    }
    if (lane == 0) {
        g_w[i0] = __expf(p[0]);
        if (base + 1 < total) g_w[i1] = __expf(p[1]);
        if (base + 2 < total) g_w[i2] = __expf(p[2]);
        if (base + 3 < total) g_w[i3] = __expf(p[3]);
    }
}

// ---------------- per-node aggregation: warp/node, 4-way slot unroll --------------------
__global__ void k_agg(const float* __restrict__ bias, int hout_id,
                      int dopool, const int* __restrict__ batch, float* __restrict__ dout) {
    int tid = threadIdx.x;
    int warp = tid >> 5, lane = tid & 31;
    int n = blockIdx.x * (blockDim.x >> 5) + warp;
    if (n >= Nn) return;
    int c0 = lane * 4;
    const float* xl = g_xl;
    float* hout = bufsel(hout_id);

    float s[4] = {0.f, 0.f, 0.f, 0.f};
    float a0[4] = {0.f, 0.f, 0.f, 0.f};
    float a1[4] = {0.f, 0.f, 0.f, 0.f};
    float a2[4] = {0.f, 0.f, 0.f, 0.f};
    float a3[4] = {0.f, 0.f, 0.f, 0.f};
    int beg = g_off[n], end = g_off[n + 1];

    for (int it = beg; it < end; it += 4) {
#pragma unroll
        for (int q = 0; q < 4; q++) {
            int iq = it + q;
            bool ok = (iq < end);
            int idx = ok ? iq : (end - 1);
            int src = g_srcs[idx];
            float w = ok ? g_w[idx] : 0.f;
            float4 v = *(const float4*)(xl + (size_t)src * Hh + c0);
            s[q] += w;
            a0[q] += w * v.x; a1[q] += w * v.y; a2[q] += w * v.z; a3[q] += w * v.w;
        }
    }

    float inv = 1.0f / (s[0] + s[1] + s[2] + s[3]);
    float o0 = fmaxf((a0[0] + a0[1] + a0[2] + a0[3]) * inv + bias[c0],     0.0f);
    float o1 = fmaxf((a1[0] + a1[1] + a1[2] + a1[3]) * inv + bias[c0 + 1], 0.0f);
    float o2 = fmaxf((a2[0] + a2[1] + a2[2] + a2[3]) * inv + bias[c0 + 2], 0.0f);
    float o3 = fmaxf((a3[0] + a3[1] + a3[2] + a3[3]) * inv + bias[c0 + 3], 0.0f);
    *(float4*)(hout + (size_t)n * Hh + c0) = make_float4(o0, o1, o2, o3);

    if (dopool) {
        int b = batch[n];
        int* dp = (int*)(dout + (size_t)b * Hh + c0);
        atomicMax(dp,     __float_as_int(o0));
        atomicMax(dp + 1, __float_as_int(o1));
        atomicMax(dp + 2, __float_as_int(o2));
        atomicMax(dp + 3, __float_as_int(o3));
    }
}

// ---------------- host launcher (kernel launches only; graph-capture safe) ----------------
extern "C" void kernel_launch(void* const* d_in, const int* in_sizes, int n_in,
                              void* d_out, int out_size) {
    const float* x        = (const float*)d_in[0];
    const int*   ei       = (const int*)d_in[1];
    const float* ea       = (const float*)d_in[2];
    const int*   batch    = (const int*)d_in[3];
    const float* atom_emb = (const float*)d_in[4];
    const float* bond_emb = (const float*)d_in[5];
    const float* bool_emb = (const float*)d_in[6];
    const float* Wn  = (const float*)d_in[7];
    const float* bn  = (const float*)d_in[8];
    const float* We  = (const float*)d_in[9];
    const float* be  = (const float*)d_in[10];
    const float* Wl1 = (const float*)d_in[11];
    const float* bl1 = (const float*)d_in[12];
    const float* Wr1 = (const float*)d_in[13];
    const float* br1 = (const float*)d_in[14];
    const float* Wedge1 = (const float*)d_in[15];
    const float* att1   = (const float*)d_in[16];
    const float* bias1  = (const float*)d_in[17];
    const float* Wl2 = (const float*)d_in[18];
    const float* bl2 = (const float*)d_in[19];
    const float* Wr2 = (const float*)d_in[20];
    const float* br2 = (const float*)d_in[21];
    const float* Wedge2 = (const float*)d_in[22];
    const float* att2   = (const float*)d_in[23];
    const float* bias2  = (const float*)d_in[24];
    float* out = (float*)d_out;

    int gm = (Nn + 63) / 64;
    int ga = (Nn + 7) / 8;
    int nb = (Nn + 1023) / 1024;
    int gs = ((Ee + Nn + 3) / 4 * 32 + 255) / 256;   // k_score: warp per 4 slots

    // prep; layer-1 GEMM kept as 4th launch (ncu window) — clock canary
    k_init_nodes<<<(Gg * Hh + 255) / 256, 256>>>(x, atom_emb, bool_emb, Wn, bn, out);
    k_enc_edges<<<(Ee + 255) / 256, 256>>>(ea, ei, bond_emb, bool_emb, We, be);
    k_scan1<<<nb, 1024>>>();
    k_gemm2<<<gm, 256>>>(BUF_H0, ND, Wl1, bl1, Wr1, br1);       // layer 1 GEMM (4th launch)
    k_scan23<<<nb, 1024>>>();
    k_scatter<<<(Ee + 255) / 256, 256>>>(ei);
    k_loopattr<<<ga, 256>>>();

    // layer 1: scores then aggregate
    k_score<<<gs, 256>>>(Wedge1, att1);
    k_agg<<<ga, 256>>>(bias1, BUF_HA, 0, batch, out);

    // layer 2 (shared weights W*2)
    k_gemm2<<<gm, 256>>>(BUF_HA, Hh, Wl2, bl2, Wr2, br2);
    k_score<<<gs, 256>>>(Wedge2, att2);
    k_agg<<<ga, 256>>>(bias2, BUF_HB, 0, batch, out);

    // layer 3 (shared weights W*2) + fused global max pool
    k_gemm2<<<gm, 256>>>(BUF_HB, Hh, Wl2, bl2, Wr2, br2);
    k_score<<<gs, 256>>>(Wedge2, att2);
    k_agg<<<ga, 256>>>(bias2, BUF_HA, 1, batch, out);
}